// round 13
// baseline (speedup 1.0000x reference)
#include <cuda_runtime.h>
#include <cstdint>

#define T_DATA 10000
#define SUB    20
#define SUBM   19
#define E_NO   2000
#define I_NO   500
#define TSYN   200
#define BNO    3
#define CHF    128
#define NCF    79             // 79*128 = 10112 >= 10000
#define TPAD   (NCF*CHF)
#define DEGM   12
#define FULLM  0xffffffffu
#define KLOG   (-1.44269504f)   // -log2(e)

typedef unsigned long long u64;

// -------- device scratch (allocations forbidden) --------
__device__ float    g_in_eT[SUB * T_DATA];
__device__ float    g_in_iT[SUB * T_DATA];
__device__ float    g_syn_s[TPAD * SUB];     // [t][20]; col j = subunit j+1, col 19 pad(0)
__device__ float    g_syn_ns[TPAD * SUB];    // [t][20]
__device__ float    g_syn_kern[SUB * 2 * TSYN];
__device__ int      g_idx_e[E_NO];
__device__ int      g_idx_i[I_NO];
__device__ unsigned g_child_mask[SUB];
__device__ int      g_ylist[SUB][DEGM];
__device__ int      g_zlist[SUBM][DEGM];
__device__ int      g_degmax;

// ---------------- K0: setup ----------------
__global__ void k0_setup(const float* __restrict__ C_den,
                         const float* __restrict__ C_syn_e,
                         const float* __restrict__ C_syn_i,
                         const float* __restrict__ W_ns_syn,
                         const float* __restrict__ Delta_ns_syn) {
    int tid = threadIdx.x;  // 256
    if (tid == 0) g_degmax = 0;
    __syncthreads();
    for (int e = tid; e < E_NO; e += 256) {
        int ix = 0;
        for (int s = 0; s < SUB; s++) if (C_syn_e[s * E_NO + e] > 0.5f) ix = s;
        g_idx_e[e] = ix;
    }
    for (int e = tid; e < I_NO; e += 256) {
        int ix = 0;
        for (int s = 0; s < SUB; s++) if (C_syn_i[s * I_NO + e] > 0.5f) ix = s;
        g_idx_i[e] = ix;
    }
    for (int i = tid; i < SUB * 2 * TSYN; i += 256) {
        int s = i / (2 * TSYN);
        int c = (i / TSYN) % 2;
        int t = i % TSYN;
        float delta = expf(Delta_ns_syn[s * 2 + c]);
        float ts = fmaxf((float)t - delta, 0.0f);
        float acc = 0.0f;
        for (int b = 0; b < BNO; b++) {
            float tau = expf((float)b);
            float tt = ts / tau;
            acc += W_ns_syn[s * (BNO * 2) + b * 2 + c] * tt * expf(-tt);
        }
        g_syn_kern[i] = acc;
    }
    if (tid < SUB) {
        unsigned cm = 0;
        for (int j = 0; j < SUBM; j++) if (C_den[tid * SUB + 1 + j] != 0.0f) cm |= 1u << j;
        g_child_mask[tid] = cm;
        int n = 0;
        for (int j = 0; j < SUB; j++)
            if (C_den[tid * SUB + j] != 0.0f && n < DEGM) g_ylist[tid][n++] = j;
        atomicMax(&g_degmax, n);
        for (; n < DEGM; n++) g_ylist[tid][n] = 31;
    }
    if (tid < SUBM) {
        int n = 0;
        for (int j = 0; j < SUBM; j++)
            if (C_den[(1 + tid) * SUB + 1 + j] != 0.0f && n < DEGM) g_zlist[tid][n++] = j;
        atomicMax(&g_degmax, n);
        for (; n < DEGM; n++) g_zlist[tid][n] = 31;
    }
}

// ---------------- K1: one-hot segment sum ----------------
__global__ void k1_bin(const float* __restrict__ S_e,
                       const float* __restrict__ S_i,
                       const float* __restrict__ W_s_syn) {
    __shared__ float bE[8][SUB];
    __shared__ float bI[8][SUB];
    int tid = threadIdx.x;
    int t0 = blockIdx.x * 8;
    for (int i = tid; i < 8 * SUB; i += 256) { (&bE[0][0])[i] = 0.0f; (&bI[0][0])[i] = 0.0f; }
    __syncthreads();
    for (int e = tid; e < E_NO; e += 256) {
        int ix = g_idx_e[e];
        for (int r = 0; r < 8; r++) {
            float v = S_e[(size_t)(t0 + r) * E_NO + e];
            if (v != 0.0f) atomicAdd(&bE[r][ix], v);
        }
    }
    for (int e = tid; e < I_NO; e += 256) {
        int ix = g_idx_i[e];
        for (int r = 0; r < 8; r++) {
            float v = S_i[(size_t)(t0 + r) * I_NO + e];
            if (v != 0.0f) atomicAdd(&bI[r][ix], v);
        }
    }
    __syncthreads();
    for (int i = tid; i < 8 * SUB; i += 256) {
        int r = i / SUB, s = i % SUB;
        int t = t0 + r;
        float ve = bE[r][s], vi = bI[r][s];
        g_in_eT[s * T_DATA + t] = ve;
        g_in_iT[s * T_DATA + t] = vi;
        if (s >= 1)
            g_syn_s[t * SUB + (s - 1)] = ve * W_s_syn[s * 2 + 0] + vi * W_s_syn[s * 2 + 1];
    }
}

// ---------------- K2: causal conv (200 taps) ----------------
__global__ void k2_conv() {
    __shared__ float ke[TSYN], ki[TSYN];
    __shared__ float xe[256 + TSYN];
    __shared__ float xi[256 + TSYN];
    int tid = threadIdx.x;
    int s = blockIdx.y;
    int t0 = blockIdx.x * 256;
    if (tid < TSYN) {
        ke[tid] = g_syn_kern[(s * 2 + 0) * TSYN + tid];
        ki[tid] = g_syn_kern[(s * 2 + 1) * TSYN + tid];
    }
    for (int j = tid; j < 256 + TSYN - 1; j += 256) {
        int g = t0 - (TSYN - 1) + j;
        bool ok = (g >= 0 && g < T_DATA);
        xe[j] = ok ? g_in_eT[s * T_DATA + g] : 0.0f;
        xi[j] = ok ? g_in_iT[s * T_DATA + g] : 0.0f;
    }
    __syncthreads();
    int t = t0 + tid;
    if (t >= T_DATA) return;
    float acc = 0.0f;
#pragma unroll 4
    for (int k = 0; k < TSYN; k++) {
        int ix = tid + (TSYN - 1) - k;
        acc = fmaf(xe[ix], ke[k], acc);
        acc = fmaf(xi[ix], ki[k], acc);
    }
    g_syn_ns[t * SUB + s] = acc;
}

// ---------------- fused kernel helpers ----------------
template<int N> __device__ __forceinline__ float psum(const float* v) {
    if constexpr (N == 1) return v[0];
    else {
        constexpr int H = N / 2, R = (N + 1) / 2;
        float t[R];
#pragma unroll
        for (int i = 0; i < H; i++) t[i] = v[2 * i] + v[2 * i + 1];
        if constexpr (N & 1) t[R - 1] = v[N - 1];
        return psum<R>(t);
    }
}
__device__ __forceinline__ void cpasync16(uint32_t saddr, const void* g) {
    asm volatile("cp.async.ca.shared.global [%0], [%1], 16;" :: "r"(saddr), "l"(g));
}
#define CP_COMMIT() asm volatile("cp.async.commit_group;")
#define CP_WAIT1()  asm volatile("cp.async.wait_group 1;")
__device__ __forceinline__ float ex2f(float x) { float r; asm("ex2.approx.f32 %0, %1;" : "=f"(r) : "f"(x)); return r; }
__device__ __forceinline__ float rcpf(float x) { float r; asm("rcp.approx.f32 %0, %1;" : "=f"(r) : "f"(x)); return r; }

// packed f32x2 (FFMA2/FADD2/FMUL2 — only reachable via PTX)
__device__ __forceinline__ u64 pk2(float lo, float hi) {
    u64 r; asm("mov.b64 %0, {%1, %2};" : "=l"(r) : "f"(lo), "f"(hi)); return r;
}
__device__ __forceinline__ void upk2(float& lo, float& hi, u64 v) {
    asm("mov.b64 {%0, %1}, %2;" : "=f"(lo), "=f"(hi) : "l"(v));
}
__device__ __forceinline__ u64 add2(u64 a, u64 b) {
    u64 r; asm("add.rn.f32x2 %0, %1, %2;" : "=l"(r) : "l"(a), "l"(b)); return r;
}
__device__ __forceinline__ u64 mul2(u64 a, u64 b) {
    u64 r; asm("mul.rn.f32x2 %0, %1, %2;" : "=l"(r) : "l"(a), "l"(b)); return r;
}
__device__ __forceinline__ u64 fma2(u64 a, u64 b, u64 c) {
    u64 r; asm("fma.rn.f32x2 %0, %1, %2, %3;" : "=l"(r) : "l"(a), "l"(b), "l"(c)); return r;
}

// staging: one chunk = CHF*SUB*4 bytes = 640 x 16B = 20 per lane
#define NSTAGE 20

// steady-state chunks have exactly CHF steps: give the compiler the constant.
template<typename F>
__device__ __forceinline__ void run_chunk(int base, F&& body) {
    if (base + CHF <= T_DATA) {
#pragma unroll 4
        for (int i = 0; i < CHF; i++) body(i);
    } else {
        int steps = T_DATA - base;
        for (int i = 0; i < steps; i++) body(i);
    }
}

// smem word offsets (all rings depth 2 x CHF=128)
#define W_CNT   0
#define W_ZRING 32
#define W_ZB    (W_ZRING + 64 + TPAD)
#define W_NB    (W_ZB + 2*CHF*SUB)
#define W_SA    (W_NB + 2*CHF*SUB)
#define W_SH    (W_SA + 2*CHF*SUB)
#define W_XR    (W_SH + 2*CHF*SUB)
#define W_SG    (W_XR + 2*CHF*SUB)
#define SMEM_WORDS (W_SG + 2*CHF*SUB)
// counters
#define C_Z  0
#define C_U  1
#define C_H  2
#define C_Y  3
#define C_WX 4
#define C_WY 5

__device__ __forceinline__ void waitGE(volatile int* p, int v) {
    while (*p < v) { __nanosleep(32); }
    __threadfence_block();
}
__device__ __forceinline__ void publish(volatile int* p, int v, int lane) {
    __threadfence_block();
    if (lane == 0) *p = v;
}

// ---- Z recursion (warp 0) ----
template<int DEG>
__device__ __forceinline__ void z_role(int lane, const float* Theta_s, const float* W_s_prop,
                                       const float* spike_decay, float* xring, int* zring,
                                       volatile int* cnt, float* zb) {
    bool active = lane < SUBM;
    float decay = active ? spike_decay[lane] : 0.0f;
    float thsyn = active ? Theta_s[lane] : 0.0f;
    int wbits = active ? __float_as_int(W_s_prop[lane]) : 0;
    int idx[DEG];
#pragma unroll
    for (int k = 0; k < DEG; k++) idx[k] = active ? g_zlist[lane][k] : 31;

    uint32_t zb0 = (uint32_t)__cvta_generic_to_shared(zb);
#pragma unroll
    for (int j = 0; j < NSTAGE; j++)
        cpasync16(zb0 + (lane + 32 * j) * 16, (const char*)g_syn_s + (lane + 32 * j) * 16);
    CP_COMMIT();
#pragma unroll
    for (int j = 0; j < NSTAGE; j++)
        cpasync16(zb0 + CHF * SUB * 4 + (lane + 32 * j) * 16,
                  (const char*)g_syn_s + (size_t)CHF * SUB * 4 + (lane + 32 * j) * 16);
    CP_COMMIT();

    float x = 0.0f, val = 0.0f;
    for (int c = 0; c < NCF; c++) {
        if (c >= 2) waitGE(&cnt[C_WX], c - 1);
        CP_WAIT1();
        __syncwarp();
        const float* sd = zb + (c & 1) * (CHF * SUB);
        float* xr = xring + (c & 1) * (CHF * SUB);
        int base = c * CHF;
        run_chunk(base, [&](int i) {
            float syn = active ? sd[i * SUB + lane] : 0.0f;
            float g[DEG];
#pragma unroll
            for (int k = 0; k < DEG; k++) g[k] = __shfl_sync(FULLM, val, idx[k]);
            float prop = psum<DEG>(g);
            float xin = fmaf(x, decay, syn + thsyn) + prop;
            int xb = __float_as_int(xin);
            val = __int_as_float(wbits & ~(xb >> 31));   // z ? wprop : 0 (sign-bit)
            x = fminf(xin, 0.0f);                        // z ? 0 : xin
            unsigned zp = __ballot_sync(FULLM, (xb >= 0) && active);
            if (active) xr[i * SUB + lane] = x;
            if (lane == 0) zring[64 + base + i] = (int)zp;
        });
        __syncwarp();
        if (c + 2 < NCF) {
            uint32_t dst = zb0 + (c & 1) * (CHF * SUB * 4);
            const char* src = (const char*)g_syn_s + (size_t)(c + 2) * CHF * SUB * 4;
#pragma unroll
            for (int j = 0; j < NSTAGE; j++)
                cpasync16(dst + (lane + 32 * j) * 16, src + (lane + 32 * j) * 16);
        }
        CP_COMMIT();
        publish(&cnt[C_Z], c + 1, lane);
    }
}

// ---- Y recursion (warp 3): KLOG pre-scaled inputs -> ex2/rcp, hval carried ----
template<int DEG>
__device__ __forceinline__ void y_role(int lane, const float* W_ns_sub,
                                       const float* sA, const float* sH,
                                       float* sgring, volatile int* cnt) {
    bool active = lane < SUB;
    float kw = active ? (KLOG * W_ns_sub[lane]) : 0.0f;
    int idx[DEG];
#pragma unroll
    for (int k = 0; k < DEG; k++) idx[k] = active ? g_ylist[lane][k] : 31;

    float hval = 0.0f;      // = kw * sig carried from previous step
    for (int c = 0; c < NCF; c++) {
        waitGE(&cnt[C_U], c + 1);
        waitGE(&cnt[C_H], c + 1);
        if (c >= 2) waitGE(&cnt[C_WY], c - 1);
        const float* aA = sA + (c & 1) * (CHF * SUB);
        const float* aH = sH + (c & 1) * (CHF * SUB);
        float* sg = sgring + (c & 1) * (CHF * SUB);
        int base = c * CHF;
        run_chunk(base, [&](int i) {
            float a = active ? (aA[i * SUB + lane] + aH[i * SUB + lane]) : 0.0f;
            float g[DEG];
#pragma unroll
            for (int k = 0; k < DEG; k++) g[k] = __shfl_sync(FULLM, hval, idx[k]);
            float xs = a + psum<DEG>(g);     // = -log2(e) * xin
            float e = ex2f(xs);              // = exp(-xin)
            float sig = rcpf(1.0f + e);
            hval = kw * sig;
            if (active) sg[i * SUB + lane] = sig;
        });
        __syncwarp();
        publish(&cnt[C_Y], c + 1, lane);
    }
}

// One block, 256 threads. W0=Z, W1=prop IIR, W2=hist IIR, W3=Y, W5=Z/X writer, W6=Y writer.
__global__ void __launch_bounds__(256, 1)
kfuse(const float* __restrict__ Theta_s,
      const float* __restrict__ W_s_prop,
      const float* __restrict__ spike_decay,
      const float* __restrict__ Theta_ns,
      const float* __restrict__ W_ns_prop,
      const float* __restrict__ W_ns_hist,
      const float* __restrict__ W_ns_sub,
      const float* __restrict__ V_o,
      float* __restrict__ out) {
    extern __shared__ int smem[];
    volatile int* cnt = (volatile int*)&smem[W_CNT];
    int* zring = &smem[W_ZRING];          // zring[64 + t]
    float* zb = (float*)&smem[W_ZB];
    float* nb = (float*)&smem[W_NB];
    float* sA = (float*)&smem[W_SA];
    float* sH = (float*)&smem[W_SH];
    float* xring = (float*)&smem[W_XR];
    float* sgring = (float*)&smem[W_SG];

    int tid = threadIdx.x;
    int wid = tid >> 5;
    int lane = tid & 31;

    if (tid < 64) zring[tid] = 0;
    if (tid < 8) ((int*)cnt)[tid] = 0;
    __syncthreads();
    int degmax = g_degmax;   // uniform

    if (wid == 0) {
        if (degmax <= 8) z_role<8>(lane, Theta_s, W_s_prop, spike_decay, xring, zring, cnt, zb);
        else             z_role<12>(lane, Theta_s, W_s_prop, spike_decay, xring, zring, cnt, zb);
    } else if (wid == 1) {
        // ------ prop IIR (packed f32x2) -> sA = KLOG*(syn_ns + Theta_ns + f_prop) ------
        bool active = (lane < SUB);
        unsigned cm = active ? g_child_mask[lane] : 0u;
        float thnk = active ? (KLOG * Theta_ns[lane]) : 0.0f;
        u64 AL2[BNO], K1[BNO], K2[BNO], P[BNO], Q[BNO];
#pragma unroll
        for (int b = 0; b < BNO; b++) {
            float tau = expf((float)b);
            float al = expf(-1.0f / tau);
            float a49 = expf(-49.0f / tau);
            float wp = active ? W_ns_prop[lane * BNO + b] : 0.0f;
            float Aq = KLOG * wp / tau;
            float Bq = Aq * a49;
            float Cq = 49.0f * Bq;
            AL2[b] = pk2(al, al);
            K1[b] = pk2(Aq, -Bq);
            K2[b] = pk2(0.0f, -Cq);
            P[b] = 0ull;
            Q[b] = 0ull;
        }

        uint32_t nb0 = (uint32_t)__cvta_generic_to_shared(nb);
#pragma unroll
        for (int j = 0; j < NSTAGE; j++)
            cpasync16(nb0 + (lane + 32 * j) * 16, (const char*)g_syn_ns + (lane + 32 * j) * 16);
        CP_COMMIT();
#pragma unroll
        for (int j = 0; j < NSTAGE; j++)
            cpasync16(nb0 + CHF * SUB * 4 + (lane + 32 * j) * 16,
                      (const char*)g_syn_ns + (size_t)CHF * SUB * 4 + (lane + 32 * j) * 16);
        CP_COMMIT();

        for (int c = 0; c < NCF; c++) {
            waitGE(&cnt[C_Z], c + 1);
            if (c >= 2) waitGE(&cnt[C_Y], c - 1);
            CP_WAIT1();
            __syncwarp();
            const float* nd = nb + (c & 1) * (CHF * SUB);
            float* dst = sA + (c & 1) * (CHF * SUB);
            int base = c * CHF;
            run_chunk(base, [&](int i) {
                int t = base + i;
                unsigned zm1  = (unsigned)zring[64 + t - 1];
                unsigned zm50 = (unsigned)zring[64 + t - 50];
                float v = (float)__popc(cm & zm1);
                float w = (float)__popc(cm & zm50);
                u64 U = pk2(v, w);
                u64 Facc = 0ull;
#pragma unroll
                for (int b = 0; b < BNO; b++) {
                    Facc = fma2(K1[b], Q[b], Facc);
                    Facc = fma2(K2[b], P[b], Facc);
                    u64 T = add2(P[b], U);
                    Q[b] = mul2(AL2[b], add2(Q[b], T));
                    P[b] = mul2(AL2[b], T);
                }
                float flo, fhi;
                upk2(flo, fhi, Facc);
                float F = thnk + flo + fhi;
                if (active) dst[i * SUB + lane] = fmaf(KLOG, nd[i * SUB + lane], F);
            });
            __syncwarp();
            if (c + 2 < NCF) {
                uint32_t d2 = nb0 + (c & 1) * (CHF * SUB * 4);
                const char* src = (const char*)g_syn_ns + (size_t)(c + 2) * CHF * SUB * 4;
#pragma unroll
                for (int j = 0; j < NSTAGE; j++)
                    cpasync16(d2 + (lane + 32 * j) * 16, src + (lane + 32 * j) * 16);
            }
            CP_COMMIT();
            publish(&cnt[C_U], c + 1, lane);
        }
    } else if (wid == 2) {
        // ------ hist IIR (packed f32x2) -> sH = KLOG * f_hist ------
        bool active = (lane >= 1 && lane < SUB);
        int sh = active ? (lane - 1) : 0;
        u64 AL2[BNO], K1[BNO], K2[BNO], P[BNO], Q[BNO];
#pragma unroll
        for (int b = 0; b < BNO; b++) {
            float tau = expf((float)b);
            float al = expf(-1.0f / tau);
            float a49 = expf(-49.0f / tau);
            float wh = active ? W_ns_hist[sh * BNO + b] : 0.0f;
            float Aq = KLOG * wh / tau;
            float Bq = Aq * a49;
            float Cq = 49.0f * Bq;
            AL2[b] = pk2(al, al);
            K1[b] = pk2(Aq, -Bq);
            K2[b] = pk2(0.0f, -Cq);
            P[b] = 0ull;
            Q[b] = 0ull;
        }
        for (int c = 0; c < NCF; c++) {
            waitGE(&cnt[C_Z], c + 1);
            if (c >= 2) waitGE(&cnt[C_Y], c - 1);
            float* dst = sH + (c & 1) * (CHF * SUB);
            int base = c * CHF;
            run_chunk(base, [&](int i) {
                int t = base + i;
                unsigned zm1  = (unsigned)zring[64 + t - 1];
                unsigned zm50 = (unsigned)zring[64 + t - 50];
                float v = (float)((zm1 >> sh) & 1u);
                float w = (float)((zm50 >> sh) & 1u);
                u64 U = pk2(v, w);
                u64 Facc = 0ull;
#pragma unroll
                for (int b = 0; b < BNO; b++) {
                    Facc = fma2(K1[b], Q[b], Facc);
                    Facc = fma2(K2[b], P[b], Facc);
                    u64 T = add2(P[b], U);
                    Q[b] = mul2(AL2[b], add2(Q[b], T));
                    P[b] = mul2(AL2[b], T);
                }
                float flo, fhi;
                upk2(flo, fhi, Facc);
                if (lane < SUB) dst[i * SUB + lane] = flo + fhi;
            });
            __syncwarp();
            publish(&cnt[C_H], c + 1, lane);
        }
    } else if (wid == 3) {
        if (degmax <= 8) y_role<8>(lane, W_ns_sub, sA, sH, sgring, cnt);
        else             y_role<12>(lane, W_ns_sub, sA, sH, sgring, cnt);
    } else if (wid == 5) {
        // ---------------- writer: outZ / outX from xring + zring ----------------
        float* outZ = out + T_DATA + T_DATA * SUBM;
        float* outX = outZ + T_DATA * SUBM;
        bool active = lane < SUBM;
        for (int c = 0; c < NCF; c++) {
            waitGE(&cnt[C_Z], c + 1);
            const float* xr = xring + (c & 1) * (CHF * SUB);
            int base = c * CHF;
            run_chunk(base, [&](int i) {
                int t = base + i;
                if (active) {
                    unsigned zp = (unsigned)zring[64 + t];
                    outZ[t * SUBM + lane] = (float)((zp >> lane) & 1u);
                    outX[t * SUBM + lane] = xr[i * SUB + lane];
                }
            });
            publish(&cnt[C_WX], c + 1, lane);
        }
    } else if (wid == 6) {
        // ---------------- writer: fv / outY from sgring ----------------
        float* fv = out;
        float* outY = out + T_DATA;
        bool active = lane < SUB;
        float wsub = active ? W_ns_sub[lane] : 0.0f;
        float vo = V_o[0];
        for (int c = 0; c < NCF; c++) {
            waitGE(&cnt[C_Y], c + 1);
            const float* sg = sgring + (c & 1) * (CHF * SUB);
            int base = c * CHF;
            run_chunk(base, [&](int i) {
                int t = base + i;
                float y = active ? wsub * sg[i * SUB + lane] : 0.0f;
                if (lane == 0)    fv[t] = y + vo;
                else if (active)  outY[t * SUBM + (lane - 1)] = y;
            });
            publish(&cnt[C_WY], c + 1, lane);
        }
    }
    // wids 4, 7: exit immediately
}

// ---------------- launch ----------------
extern "C" void kernel_launch(void* const* d_in, const int* in_sizes, int n_in,
                              void* d_out, int out_size) {
    const float* S_e          = (const float*)d_in[0];
    const float* S_i          = (const float*)d_in[1];
    const float* C_den        = (const float*)d_in[2];
    const float* C_syn_e      = (const float*)d_in[3];
    const float* C_syn_i      = (const float*)d_in[4];
    const float* W_s_syn      = (const float*)d_in[5];
    const float* W_ns_syn     = (const float*)d_in[6];
    const float* Delta_ns_syn = (const float*)d_in[7];
    const float* W_ns_sub     = (const float*)d_in[8];
    const float* V_o          = (const float*)d_in[9];
    const float* Theta_s      = (const float*)d_in[10];
    const float* Theta_ns     = (const float*)d_in[11];
    const float* W_ns_hist    = (const float*)d_in[12];
    const float* W_s_prop     = (const float*)d_in[13];
    const float* W_ns_prop    = (const float*)d_in[14];
    const float* spike_decay  = (const float*)d_in[15];
    float* out = (float*)d_out;

    static bool attr_done = false;
    if (!attr_done) {
        cudaFuncSetAttribute(kfuse, cudaFuncAttributeMaxDynamicSharedMemorySize,
                             SMEM_WORDS * 4);
        attr_done = true;
    }

    k0_setup<<<1, 256>>>(C_den, C_syn_e, C_syn_i, W_ns_syn, Delta_ns_syn);
    k1_bin<<<T_DATA / 8, 256>>>(S_e, S_i, W_s_syn);
    k2_conv<<<dim3((T_DATA + 255) / 256, SUB), 256>>>();
    kfuse<<<1, 256, SMEM_WORDS * 4>>>(Theta_s, W_s_prop, spike_decay, Theta_ns,
                                      W_ns_prop, W_ns_hist, W_ns_sub, V_o, out);
}

// round 14
// speedup vs baseline: 1.0176x; 1.0176x over previous
#include <cuda_runtime.h>
#include <cstdint>

#define T_DATA 10000
#define SUB    20
#define SUBM   19
#define E_NO   2000
#define I_NO   500
#define TSYN   200
#define BNO    3
#define CHF    128
#define NCF    79             // 79*128 = 10112 >= 10000
#define TPAD   (NCF*CHF)
#define DEGM   12
#define FULLM  0xffffffffu
#define KLOG   (-1.44269504f)   // -log2(e)

// -------- device scratch (allocations forbidden) --------
__device__ float    g_in_eT[SUB * T_DATA];
__device__ float    g_in_iT[SUB * T_DATA];
__device__ float    g_syn_s[TPAD * SUB];     // [t][20]; col j = subunit j+1, col 19 pad(0)
__device__ float    g_syn_ns[TPAD * SUB];    // [t][20]
__device__ float    g_syn_kern[SUB * 2 * TSYN];
__device__ int      g_idx_e[E_NO];
__device__ int      g_idx_i[I_NO];
__device__ unsigned g_child_mask[SUB];
__device__ int      g_ylist[SUB][DEGM];
__device__ int      g_zlist[SUBM][DEGM];
__device__ int      g_degmax;

// ---------------- K0: setup (parallel across 80 blocks) ----------------
__global__ void k0_setup(const float* __restrict__ C_den,
                         const float* __restrict__ C_syn_e,
                         const float* __restrict__ C_syn_i,
                         const float* __restrict__ W_ns_syn,
                         const float* __restrict__ Delta_ns_syn) {
    int tid = threadIdx.x;                 // 256
    int gstride = gridDim.x * blockDim.x;
    int gtid = blockIdx.x * blockDim.x + tid;

    for (int e = gtid; e < E_NO; e += gstride) {
        int ix = 0;
        for (int s = 0; s < SUB; s++) if (C_syn_e[s * E_NO + e] > 0.5f) ix = s;
        g_idx_e[e] = ix;
    }
    for (int e = gtid; e < I_NO; e += gstride) {
        int ix = 0;
        for (int s = 0; s < SUB; s++) if (C_syn_i[s * I_NO + e] > 0.5f) ix = s;
        g_idx_i[e] = ix;
    }
    for (int i = gtid; i < SUB * 2 * TSYN; i += gstride) {
        int s = i / (2 * TSYN);
        int c = (i / TSYN) % 2;
        int t = i % TSYN;
        float delta = expf(Delta_ns_syn[s * 2 + c]);
        float ts = fmaxf((float)t - delta, 0.0f);
        float acc = 0.0f;
        for (int b = 0; b < BNO; b++) {
            float tau = expf((float)b);
            float tt = ts / tau;
            acc += W_ns_syn[s * (BNO * 2) + b * 2 + c] * tt * expf(-tt);
        }
        g_syn_kern[i] = acc;
    }

    if (blockIdx.x == 0) {
        if (tid == 0) g_degmax = 0;
        __syncthreads();
        if (tid < SUB) {
            unsigned cm = 0;
            for (int j = 0; j < SUBM; j++) if (C_den[tid * SUB + 1 + j] != 0.0f) cm |= 1u << j;
            g_child_mask[tid] = cm;
            int n = 0;
            for (int j = 0; j < SUB; j++)
                if (C_den[tid * SUB + j] != 0.0f && n < DEGM) g_ylist[tid][n++] = j;
            atomicMax(&g_degmax, n);
            for (; n < DEGM; n++) g_ylist[tid][n] = 31;
        }
        if (tid < SUBM) {
            int n = 0;
            for (int j = 0; j < SUBM; j++)
                if (C_den[(1 + tid) * SUB + 1 + j] != 0.0f && n < DEGM) g_zlist[tid][n++] = j;
            atomicMax(&g_degmax, n);
            for (; n < DEGM; n++) g_zlist[tid][n] = 31;
        }
    }
}

// ---------------- K1: one-hot segment sum ----------------
__global__ void k1_bin(const float* __restrict__ S_e,
                       const float* __restrict__ S_i,
                       const float* __restrict__ W_s_syn) {
    __shared__ float bE[8][SUB];
    __shared__ float bI[8][SUB];
    int tid = threadIdx.x;
    int t0 = blockIdx.x * 8;
    for (int i = tid; i < 8 * SUB; i += 256) { (&bE[0][0])[i] = 0.0f; (&bI[0][0])[i] = 0.0f; }
    __syncthreads();
    for (int e = tid; e < E_NO; e += 256) {
        int ix = g_idx_e[e];
        for (int r = 0; r < 8; r++) {
            float v = S_e[(size_t)(t0 + r) * E_NO + e];
            if (v != 0.0f) atomicAdd(&bE[r][ix], v);
        }
    }
    for (int e = tid; e < I_NO; e += 256) {
        int ix = g_idx_i[e];
        for (int r = 0; r < 8; r++) {
            float v = S_i[(size_t)(t0 + r) * I_NO + e];
            if (v != 0.0f) atomicAdd(&bI[r][ix], v);
        }
    }
    __syncthreads();
    for (int i = tid; i < 8 * SUB; i += 256) {
        int r = i / SUB, s = i % SUB;
        int t = t0 + r;
        float ve = bE[r][s], vi = bI[r][s];
        g_in_eT[s * T_DATA + t] = ve;
        g_in_iT[s * T_DATA + t] = vi;
        if (s >= 1)
            g_syn_s[t * SUB + (s - 1)] = ve * W_s_syn[s * 2 + 0] + vi * W_s_syn[s * 2 + 1];
    }
}

// ---------------- K2: causal conv (200 taps) ----------------
__global__ void k2_conv() {
    __shared__ float ke[TSYN], ki[TSYN];
    __shared__ float xe[256 + TSYN];
    __shared__ float xi[256 + TSYN];
    int tid = threadIdx.x;
    int s = blockIdx.y;
    int t0 = blockIdx.x * 256;
    if (tid < TSYN) {
        ke[tid] = g_syn_kern[(s * 2 + 0) * TSYN + tid];
        ki[tid] = g_syn_kern[(s * 2 + 1) * TSYN + tid];
    }
    for (int j = tid; j < 256 + TSYN - 1; j += 256) {
        int g = t0 - (TSYN - 1) + j;
        bool ok = (g >= 0 && g < T_DATA);
        xe[j] = ok ? g_in_eT[s * T_DATA + g] : 0.0f;
        xi[j] = ok ? g_in_iT[s * T_DATA + g] : 0.0f;
    }
    __syncthreads();
    int t = t0 + tid;
    if (t >= T_DATA) return;
    float acc = 0.0f;
#pragma unroll 4
    for (int k = 0; k < TSYN; k++) {
        int ix = tid + (TSYN - 1) - k;
        acc = fmaf(xe[ix], ke[k], acc);
        acc = fmaf(xi[ix], ki[k], acc);
    }
    g_syn_ns[t * SUB + s] = acc;
}

// ---------------- fused kernel helpers ----------------
template<int N> __device__ __forceinline__ float psum(const float* v) {
    if constexpr (N == 1) return v[0];
    else {
        constexpr int H = N / 2, R = (N + 1) / 2;
        float t[R];
#pragma unroll
        for (int i = 0; i < H; i++) t[i] = v[2 * i] + v[2 * i + 1];
        if constexpr (N & 1) t[R - 1] = v[N - 1];
        return psum<R>(t);
    }
}
__device__ __forceinline__ void cpasync16(uint32_t saddr, const void* g) {
    asm volatile("cp.async.ca.shared.global [%0], [%1], 16;" :: "r"(saddr), "l"(g));
}
#define CP_COMMIT() asm volatile("cp.async.commit_group;")
#define CP_WAIT1()  asm volatile("cp.async.wait_group 1;")
__device__ __forceinline__ float ex2f(float x) { float r; asm("ex2.approx.f32 %0, %1;" : "=f"(r) : "f"(x)); return r; }
__device__ __forceinline__ float rcpf(float x) { float r; asm("rcp.approx.f32 %0, %1;" : "=f"(r) : "f"(x)); return r; }

// staging: one chunk = CHF*SUB*4 bytes = 640 x 16B = 20 per lane
#define NSTAGE 20

// steady-state chunks have exactly CHF steps: give the compiler the constant.
template<typename F>
__device__ __forceinline__ void run_chunk(int base, F&& body) {
    if (base + CHF <= T_DATA) {
#pragma unroll 4
        for (int i = 0; i < CHF; i++) body(i);
    } else {
        int steps = T_DATA - base;
        for (int i = 0; i < steps; i++) body(i);
    }
}

// smem word offsets (all rings depth 2 x CHF=128)
#define W_CNT   0
#define W_ZRING 32
#define W_ZB    (W_ZRING + 64 + TPAD)
#define W_NB    (W_ZB + 2*CHF*SUB)
#define W_SA    (W_NB + 2*CHF*SUB)
#define W_SH    (W_SA + 2*CHF*SUB)
#define W_XR    (W_SH + 2*CHF*SUB)
#define W_SG    (W_XR + 2*CHF*SUB)
#define SMEM_WORDS (W_SG + 2*CHF*SUB)
// counters
#define C_Z  0
#define C_U  1
#define C_H  2
#define C_Y  3
#define C_WX 4
#define C_WY 5

__device__ __forceinline__ void waitGE(volatile int* p, int v) {
    while (*p < v) { __nanosleep(32); }
    __threadfence_block();
}
__device__ __forceinline__ void publish(volatile int* p, int v, int lane) {
    __threadfence_block();
    if (lane == 0) *p = v;
}

// ---- Z recursion (warp 0) ----
template<int DEG>
__device__ __forceinline__ void z_role(int lane, const float* Theta_s, const float* W_s_prop,
                                       const float* spike_decay, float* xring, int* zring,
                                       volatile int* cnt, float* zb) {
    bool active = lane < SUBM;
    float decay = active ? spike_decay[lane] : 0.0f;
    float thsyn = active ? Theta_s[lane] : 0.0f;
    int wbits = active ? __float_as_int(W_s_prop[lane]) : 0;
    int idx[DEG];
#pragma unroll
    for (int k = 0; k < DEG; k++) idx[k] = active ? g_zlist[lane][k] : 31;

    uint32_t zb0 = (uint32_t)__cvta_generic_to_shared(zb);
#pragma unroll
    for (int j = 0; j < NSTAGE; j++)
        cpasync16(zb0 + (lane + 32 * j) * 16, (const char*)g_syn_s + (lane + 32 * j) * 16);
    CP_COMMIT();
#pragma unroll
    for (int j = 0; j < NSTAGE; j++)
        cpasync16(zb0 + CHF * SUB * 4 + (lane + 32 * j) * 16,
                  (const char*)g_syn_s + (size_t)CHF * SUB * 4 + (lane + 32 * j) * 16);
    CP_COMMIT();

    float x = 0.0f, val = 0.0f;
    for (int c = 0; c < NCF; c++) {
        if (c >= 2) waitGE(&cnt[C_WX], c - 1);
        CP_WAIT1();
        __syncwarp();
        const float* sd = zb + (c & 1) * (CHF * SUB);
        float* xr = xring + (c & 1) * (CHF * SUB);
        int base = c * CHF;
        run_chunk(base, [&](int i) {
            float syn = active ? sd[i * SUB + lane] : 0.0f;
            float g[DEG];
#pragma unroll
            for (int k = 0; k < DEG; k++) g[k] = __shfl_sync(FULLM, val, idx[k]);
            float prop = psum<DEG>(g);
            float xin = fmaf(x, decay, syn + thsyn) + prop;
            int xb = __float_as_int(xin);
            val = __int_as_float(wbits & ~(xb >> 31));   // z ? wprop : 0 (sign-bit)
            x = fminf(xin, 0.0f);                        // z ? 0 : xin
            unsigned zp = __ballot_sync(FULLM, (xb >= 0) && active);
            if (active) xr[i * SUB + lane] = x;
            if (lane == 0) zring[64 + base + i] = (int)zp;
        });
        __syncwarp();
        if (c + 2 < NCF) {
            uint32_t dst = zb0 + (c & 1) * (CHF * SUB * 4);
            const char* src = (const char*)g_syn_s + (size_t)(c + 2) * CHF * SUB * 4;
#pragma unroll
            for (int j = 0; j < NSTAGE; j++)
                cpasync16(dst + (lane + 32 * j) * 16, src + (lane + 32 * j) * 16);
        }
        CP_COMMIT();
        publish(&cnt[C_Z], c + 1, lane);
    }
}

// ---- Y recursion (warp 3): KLOG pre-scaled inputs -> ex2/rcp, hval carried ----
template<int DEG>
__device__ __forceinline__ void y_role(int lane, const float* W_ns_sub,
                                       const float* sA, const float* sH,
                                       float* sgring, volatile int* cnt) {
    bool active = lane < SUB;
    float kw = active ? (KLOG * W_ns_sub[lane]) : 0.0f;
    int idx[DEG];
#pragma unroll
    for (int k = 0; k < DEG; k++) idx[k] = active ? g_ylist[lane][k] : 31;

    float hval = 0.0f;      // = kw * sig carried from previous step
    for (int c = 0; c < NCF; c++) {
        waitGE(&cnt[C_U], c + 1);
        waitGE(&cnt[C_H], c + 1);
        if (c >= 2) waitGE(&cnt[C_WY], c - 1);
        const float* aA = sA + (c & 1) * (CHF * SUB);
        const float* aH = sH + (c & 1) * (CHF * SUB);
        float* sg = sgring + (c & 1) * (CHF * SUB);
        int base = c * CHF;
        run_chunk(base, [&](int i) {
            float a = active ? (aA[i * SUB + lane] + aH[i * SUB + lane]) : 0.0f;
            float g[DEG];
#pragma unroll
            for (int k = 0; k < DEG; k++) g[k] = __shfl_sync(FULLM, hval, idx[k]);
            float xs = a + psum<DEG>(g);     // = -log2(e) * xin
            float e = ex2f(xs);              // = exp(-xin)
            float sig = rcpf(1.0f + e);
            hval = kw * sig;
            if (active) sg[i * SUB + lane] = sig;
        });
        __syncwarp();
        publish(&cnt[C_Y], c + 1, lane);
    }
}

// One block, 256 threads. W0=Z, W1=prop IIR, W2=hist IIR, W3=Y, W5=Z/X writer, W6=Y writer.
__global__ void __launch_bounds__(256, 1)
kfuse(const float* __restrict__ Theta_s,
      const float* __restrict__ W_s_prop,
      const float* __restrict__ spike_decay,
      const float* __restrict__ Theta_ns,
      const float* __restrict__ W_ns_prop,
      const float* __restrict__ W_ns_hist,
      const float* __restrict__ W_ns_sub,
      const float* __restrict__ V_o,
      float* __restrict__ out) {
    extern __shared__ int smem[];
    volatile int* cnt = (volatile int*)&smem[W_CNT];
    int* zring = &smem[W_ZRING];          // zring[64 + t]
    float* zb = (float*)&smem[W_ZB];
    float* nb = (float*)&smem[W_NB];
    float* sA = (float*)&smem[W_SA];
    float* sH = (float*)&smem[W_SH];
    float* xring = (float*)&smem[W_XR];
    float* sgring = (float*)&smem[W_SG];

    int tid = threadIdx.x;
    int wid = tid >> 5;
    int lane = tid & 31;

    if (tid < 64) zring[tid] = 0;
    if (tid < 8) ((int*)cnt)[tid] = 0;
    __syncthreads();
    int degmax = g_degmax;   // uniform

    if (wid == 0) {
        if (degmax <= 8) z_role<8>(lane, Theta_s, W_s_prop, spike_decay, xring, zring, cnt, zb);
        else             z_role<12>(lane, Theta_s, W_s_prop, spike_decay, xring, zring, cnt, zb);
    } else if (wid == 1) {
        // ---------------- prop IIR -> sA = KLOG*(syn_ns + Theta_ns + f_prop) ----------------
        bool active = (lane < SUB);
        unsigned cm = active ? g_child_mask[lane] : 0u;
        float thnk = active ? (KLOG * Theta_ns[lane]) : 0.0f;
        float al[BNO], Aq[BNO], Bq[BNO], Cq[BNO];
#pragma unroll
        for (int b = 0; b < BNO; b++) {
            float tau = expf((float)b);
            al[b] = expf(-1.0f / tau);
            float a49 = expf(-49.0f / tau);
            float wp = active ? W_ns_prop[lane * BNO + b] : 0.0f;
            Aq[b] = KLOG * wp / tau;
            Bq[b] = Aq[b] * a49;
            Cq[b] = 49.0f * Bq[b];
        }
        float pv[BNO] = {0, 0, 0}, qv[BNO] = {0, 0, 0};
        float pw[BNO] = {0, 0, 0}, qw[BNO] = {0, 0, 0};

        uint32_t nb0 = (uint32_t)__cvta_generic_to_shared(nb);
#pragma unroll
        for (int j = 0; j < NSTAGE; j++)
            cpasync16(nb0 + (lane + 32 * j) * 16, (const char*)g_syn_ns + (lane + 32 * j) * 16);
        CP_COMMIT();
#pragma unroll
        for (int j = 0; j < NSTAGE; j++)
            cpasync16(nb0 + CHF * SUB * 4 + (lane + 32 * j) * 16,
                      (const char*)g_syn_ns + (size_t)CHF * SUB * 4 + (lane + 32 * j) * 16);
        CP_COMMIT();

        for (int c = 0; c < NCF; c++) {
            waitGE(&cnt[C_Z], c + 1);
            if (c >= 2) waitGE(&cnt[C_Y], c - 1);
            CP_WAIT1();
            __syncwarp();
            const float* nd = nb + (c & 1) * (CHF * SUB);
            float* dst = sA + (c & 1) * (CHF * SUB);
            int base = c * CHF;
            run_chunk(base, [&](int i) {
                int t = base + i;
                unsigned zm1  = (unsigned)zring[64 + t - 1];
                unsigned zm50 = (unsigned)zring[64 + t - 50];
                float v = (float)__popc(cm & zm1);
                float w = (float)__popc(cm & zm50);
                float F = thnk;
#pragma unroll
                for (int b = 0; b < BNO; b++) {
                    F = fmaf(Aq[b], qv[b], F);
                    F = fmaf(-Bq[b], qw[b], F);
                    F = fmaf(-Cq[b], pw[b], F);
                    float tv = pv[b] + v;
                    qv[b] = al[b] * (qv[b] + tv);
                    pv[b] = al[b] * tv;
                    float tw = pw[b] + w;
                    qw[b] = al[b] * (qw[b] + tw);
                    pw[b] = al[b] * tw;
                }
                if (active) dst[i * SUB + lane] = fmaf(KLOG, nd[i * SUB + lane], F);
            });
            __syncwarp();
            if (c + 2 < NCF) {
                uint32_t d2 = nb0 + (c & 1) * (CHF * SUB * 4);
                const char* src = (const char*)g_syn_ns + (size_t)(c + 2) * CHF * SUB * 4;
#pragma unroll
                for (int j = 0; j < NSTAGE; j++)
                    cpasync16(d2 + (lane + 32 * j) * 16, src + (lane + 32 * j) * 16);
            }
            CP_COMMIT();
            publish(&cnt[C_U], c + 1, lane);
        }
    } else if (wid == 2) {
        // ---------------- hist IIR -> sH = KLOG * f_hist ----------------
        bool active = (lane >= 1 && lane < SUB);
        int sh = active ? (lane - 1) : 0;
        float al[BNO], Aq[BNO], Bq[BNO], Cq[BNO];
#pragma unroll
        for (int b = 0; b < BNO; b++) {
            float tau = expf((float)b);
            al[b] = expf(-1.0f / tau);
            float a49 = expf(-49.0f / tau);
            float wh = active ? W_ns_hist[sh * BNO + b] : 0.0f;
            Aq[b] = KLOG * wh / tau;
            Bq[b] = Aq[b] * a49;
            Cq[b] = 49.0f * Bq[b];
        }
        float pv[BNO] = {0, 0, 0}, qv[BNO] = {0, 0, 0};
        float pw[BNO] = {0, 0, 0}, qw[BNO] = {0, 0, 0};
        for (int c = 0; c < NCF; c++) {
            waitGE(&cnt[C_Z], c + 1);
            if (c >= 2) waitGE(&cnt[C_Y], c - 1);
            float* dst = sH + (c & 1) * (CHF * SUB);
            int base = c * CHF;
            run_chunk(base, [&](int i) {
                int t = base + i;
                unsigned zm1  = (unsigned)zring[64 + t - 1];
                unsigned zm50 = (unsigned)zring[64 + t - 50];
                float v = (float)((zm1 >> sh) & 1u);
                float w = (float)((zm50 >> sh) & 1u);
                float F = 0.0f;
#pragma unroll
                for (int b = 0; b < BNO; b++) {
                    F = fmaf(Aq[b], qv[b], F);
                    F = fmaf(-Bq[b], qw[b], F);
                    F = fmaf(-Cq[b], pw[b], F);
                    float tv = pv[b] + v;
                    qv[b] = al[b] * (qv[b] + tv);
                    pv[b] = al[b] * tv;
                    float tw = pw[b] + w;
                    qw[b] = al[b] * (qw[b] + tw);
                    pw[b] = al[b] * tw;
                }
                if (lane < SUB) dst[i * SUB + lane] = F;
            });
            __syncwarp();
            publish(&cnt[C_H], c + 1, lane);
        }
    } else if (wid == 3) {
        if (degmax <= 8) y_role<8>(lane, W_ns_sub, sA, sH, sgring, cnt);
        else             y_role<12>(lane, W_ns_sub, sA, sH, sgring, cnt);
    } else if (wid == 5) {
        // ---------------- writer: outZ / outX from xring + zring ----------------
        float* outZ = out + T_DATA + T_DATA * SUBM;
        float* outX = outZ + T_DATA * SUBM;
        bool active = lane < SUBM;
        for (int c = 0; c < NCF; c++) {
            waitGE(&cnt[C_Z], c + 1);
            const float* xr = xring + (c & 1) * (CHF * SUB);
            int base = c * CHF;
            run_chunk(base, [&](int i) {
                int t = base + i;
                if (active) {
                    unsigned zp = (unsigned)zring[64 + t];
                    outZ[t * SUBM + lane] = (float)((zp >> lane) & 1u);
                    outX[t * SUBM + lane] = xr[i * SUB + lane];
                }
            });
            publish(&cnt[C_WX], c + 1, lane);
        }
    } else if (wid == 6) {
        // ---------------- writer: fv / outY from sgring ----------------
        float* fv = out;
        float* outY = out + T_DATA;
        bool active = lane < SUB;
        float wsub = active ? W_ns_sub[lane] : 0.0f;
        float vo = V_o[0];
        for (int c = 0; c < NCF; c++) {
            waitGE(&cnt[C_Y], c + 1);
            const float* sg = sgring + (c & 1) * (CHF * SUB);
            int base = c * CHF;
            run_chunk(base, [&](int i) {
                int t = base + i;
                float y = active ? wsub * sg[i * SUB + lane] : 0.0f;
                if (lane == 0)    fv[t] = y + vo;
                else if (active)  outY[t * SUBM + (lane - 1)] = y;
            });
            publish(&cnt[C_WY], c + 1, lane);
        }
    }
    // wids 4, 7: exit immediately
}

// ---------------- launch ----------------
extern "C" void kernel_launch(void* const* d_in, const int* in_sizes, int n_in,
                              void* d_out, int out_size) {
    const float* S_e          = (const float*)d_in[0];
    const float* S_i          = (const float*)d_in[1];
    const float* C_den        = (const float*)d_in[2];
    const float* C_syn_e      = (const float*)d_in[3];
    const float* C_syn_i      = (const float*)d_in[4];
    const float* W_s_syn      = (const float*)d_in[5];
    const float* W_ns_syn     = (const float*)d_in[6];
    const float* Delta_ns_syn = (const float*)d_in[7];
    const float* W_ns_sub     = (const float*)d_in[8];
    const float* V_o          = (const float*)d_in[9];
    const float* Theta_s      = (const float*)d_in[10];
    const float* Theta_ns     = (const float*)d_in[11];
    const float* W_ns_hist    = (const float*)d_in[12];
    const float* W_s_prop     = (const float*)d_in[13];
    const float* W_ns_prop    = (const float*)d_in[14];
    const float* spike_decay  = (const float*)d_in[15];
    float* out = (float*)d_out;

    static bool attr_done = false;
    if (!attr_done) {
        cudaFuncSetAttribute(kfuse, cudaFuncAttributeMaxDynamicSharedMemorySize,
                             SMEM_WORDS * 4);
        attr_done = true;
    }

    k0_setup<<<80, 256>>>(C_den, C_syn_e, C_syn_i, W_ns_syn, Delta_ns_syn);
    k1_bin<<<T_DATA / 8, 256>>>(S_e, S_i, W_s_syn);
    k2_conv<<<dim3((T_DATA + 255) / 256, SUB), 256>>>();
    kfuse<<<1, 256, SMEM_WORDS * 4>>>(Theta_s, W_s_prop, spike_decay, Theta_ns,
                                      W_ns_prop, W_ns_hist, W_ns_sub, V_o, out);
}